// round 1
// baseline (speedup 1.0000x reference)
#include <cuda_runtime.h>

#define BB     32
#define NVV    6890
#define NFF    13776
#define MAXC   8
#define NCC    (NFF * MAXC)          // 110208
#define NPAIRS (BB * NCC)            // 3,526,656
#define SIGMA_F  0.5f
#define SIGMA2_F 0.25f

// Padded triangle buffer: 3 x float4 per (b, face). 32*13776*3*16B = ~21.2 MB.
__device__ float4 g_tris[(size_t)BB * NFF * 3];
__device__ double g_acc;

__global__ void zero_kernel() { g_acc = 0.0; }

__global__ __launch_bounds__(256) void build_tris_kernel(
    const float* __restrict__ verts, const int* __restrict__ faces)
{
    int t = blockIdx.x * blockDim.x + threadIdx.x;
    if (t >= BB * NFF) return;
    int b = t / NFF;
    int f = t - b * NFF;
    int i0 = faces[3 * f + 0];
    int i1 = faces[3 * f + 1];
    int i2 = faces[3 * f + 2];
    const float* vb = verts + (size_t)b * NVV * 3;
    float4 v0 = make_float4(vb[3 * i0], vb[3 * i0 + 1], vb[3 * i0 + 2], 0.f);
    float4 v1 = make_float4(vb[3 * i1], vb[3 * i1 + 1], vb[3 * i1 + 2], 0.f);
    float4 v2 = make_float4(vb[3 * i2], vb[3 * i2 + 1], vb[3 * i2 + 2], 0.f);
    float4* dst = &g_tris[(size_t)t * 3];
    dst[0] = v0; dst[1] = v1; dst[2] = v2;
}

// Penetration of query-tri vertices inside cone field of cone-tri.
// Exactly mirrors reference math: c = mean(cone verts); n = cross(e1,e2)/(||.||+1e-8);
// h = (q - c) . n; r = ||q - c||; phi = max(SIGMA - r, 0); pen = sum_v [h<0] phi h^2.
__device__ __forceinline__ float cone_pen(
    float4 a0, float4 a1, float4 a2,   // cone triangle
    float4 q0, float4 q1, float4 q2)   // query triangle
{
    const float third = 1.0f / 3.0f;
    float cx = (a0.x + a1.x + a2.x) * third;
    float cy = (a0.y + a1.y + a2.y) * third;
    float cz = (a0.z + a1.z + a2.z) * third;

    float d0x = q0.x - cx, d0y = q0.y - cy, d0z = q0.z - cz;
    float d1x = q1.x - cx, d1y = q1.y - cy, d1z = q1.z - cz;
    float d2x = q2.x - cx, d2y = q2.y - cy, d2z = q2.z - cz;

    float r20 = fmaf(d0x, d0x, fmaf(d0y, d0y, d0z * d0z));
    float r21 = fmaf(d1x, d1x, fmaf(d1y, d1y, d1z * d1z));
    float r22 = fmaf(d2x, d2x, fmaf(d2y, d2y, d2z * d2z));

    // Fast reject: phi == 0 for all three verts -> pen == 0, skip normal math.
    if (fminf(fminf(r20, r21), r22) >= SIGMA2_F) return 0.0f;

    float e1x = a1.x - a0.x, e1y = a1.y - a0.y, e1z = a1.z - a0.z;
    float e2x = a2.x - a0.x, e2y = a2.y - a0.y, e2z = a2.z - a0.z;
    float nx = e1y * e2z - e1z * e2y;
    float ny = e1z * e2x - e1x * e2z;
    float nz = e1x * e2y - e1y * e2x;
    float nn = sqrtf(fmaf(nx, nx, fmaf(ny, ny, nz * nz)));
    float inv = 1.0f / (nn + 1e-8f);
    nx *= inv; ny *= inv; nz *= inv;

    float s = 0.0f;
    if (r20 < SIGMA2_F) {
        float h = fmaf(d0x, nx, fmaf(d0y, ny, d0z * nz));
        if (h < 0.0f) { float phi = SIGMA_F - sqrtf(r20); s = fmaf(phi * h, h, s); }
    }
    if (r21 < SIGMA2_F) {
        float h = fmaf(d1x, nx, fmaf(d1y, ny, d1z * nz));
        if (h < 0.0f) { float phi = SIGMA_F - sqrtf(r21); s = fmaf(phi * h, h, s); }
    }
    if (r22 < SIGMA2_F) {
        float h = fmaf(d2x, nx, fmaf(d2y, ny, d2z * nz));
        if (h < 0.0f) { float phi = SIGMA_F - sqrtf(r22); s = fmaf(phi * h, h, s); }
    }
    return s;
}

__global__ __launch_bounds__(256) void pair_kernel(const int2* __restrict__ cidx)
{
    int p = blockIdx.x * blockDim.x + threadIdx.x;
    float pen = 0.0f;
    if (p < NPAIRS) {
        int b = p / NCC;
        int2 ids = cidx[p];
        if (ids.x >= 0) {
            int ri = ids.x;
            int ii = max(ids.y, 0);
            const float4* tr = &g_tris[((size_t)b * NFF + ri) * 3];
            const float4* ti = &g_tris[((size_t)b * NFF + ii) * 3];
            float4 r0 = tr[0], r1 = tr[1], r2 = tr[2];
            float4 i0 = ti[0], i1 = ti[1], i2 = ti[2];
            pen = cone_pen(r0, r1, r2, i0, i1, i2)
                + cone_pen(i0, i1, i2, r0, r1, r2);
        }
    }

    // warp reduce (all terms >= 0, fp32 is plenty; block partial goes to double)
    #pragma unroll
    for (int o = 16; o > 0; o >>= 1)
        pen += __shfl_down_sync(0xffffffffu, pen, o);

    __shared__ float wsum[8];
    int lane = threadIdx.x & 31;
    int w    = threadIdx.x >> 5;
    if (lane == 0) wsum[w] = pen;
    __syncthreads();
    if (w == 0) {
        float v = (lane < 8) ? wsum[lane] : 0.0f;
        #pragma unroll
        for (int o = 4; o > 0; o >>= 1)
            v += __shfl_down_sync(0xffu, v, o);
        if (lane == 0) atomicAdd(&g_acc, (double)v);
    }
}

__global__ void finalize_kernel(const float* __restrict__ weight, float* __restrict__ out)
{
    out[0] = (float)(g_acc * (1.0 / (double)BB)) * weight[0];
}

extern "C" void kernel_launch(void* const* d_in, const int* in_sizes, int n_in,
                              void* d_out, int out_size)
{
    // metadata order: pose, joints, points, keypoints, vertices, weight, faces, collision_idxs
    const float* vertices = (const float*)d_in[4];
    const float* weight   = (const float*)d_in[5];
    const int*   faces    = (const int*)d_in[6];
    const int2*  cidx     = (const int2*)d_in[7];

    zero_kernel<<<1, 1>>>();
    build_tris_kernel<<<(BB * NFF + 255) / 256, 256>>>(vertices, faces);
    pair_kernel<<<(NPAIRS + 255) / 256, 256>>>(cidx);
    finalize_kernel<<<1, 1>>>(weight, (float*)d_out);
}